// round 11
// baseline (speedup 1.0000x reference)
#include <cuda_runtime.h>
#include <cuda_bf16.h>
#include <math.h>
#include <stdint.h>

// ---------------- Problem constants ----------------
#define N_NODES 12288
#define B_BATCH 64
#define R_REG   36
#define E_EDGES 196608
#define DIN     512
#define DOUT    512
#define PDIM    256
#define DIMG    1024
#define BR      (B_BATCH * R_REG)   // 2304

// ---------------- Scratch (device globals; no allocation allowed) ----------------
__device__ __align__(16) float g_img_proj[BR * PDIM];
__device__ __align__(16) float g_img_fc[BR * DOUT];
__device__ __align__(16) float g_node_proj[N_NODES * PDIM];
__device__ __align__(16) float g_h1[N_NODES * DOUT];
__device__ __align__(16) float g_msg[N_NODES * DOUT];
__device__ int g_deg[N_NODES];
__device__ int g_cursor[N_NODES];
__device__ int g_off[N_NODES + 1];
__device__ int g_csr_src[E_EDGES];
__device__ int g_bdeg[B_BATCH];
__device__ int g_bcur[B_BATCH];
__device__ int g_boff[B_BATCH + 1];
__device__ int g_bnodes[N_NODES];
// Pre-transposed, bf16 hi/lo split weights, [N,K] row-major
__device__ __align__(16) __nv_bfloat16 g_wt_img_hi[768 * 1024];
__device__ __align__(16) __nv_bfloat16 g_wt_img_lo[768 * 1024];
__device__ __align__(16) __nv_bfloat16 g_wt_node_hi[768 * 512];
__device__ __align__(16) __nv_bfloat16 g_wt_node_lo[768 * 512];
__device__ __align__(16) __nv_bfloat16 g_wt_ap_hi[512 * 1024];
__device__ __align__(16) __nv_bfloat16 g_wt_ap_lo[512 * 1024];
// Pre-split activations, bf16 hi/lo, row-major
__device__ __align__(16) __nv_bfloat16 g_as_img_hi[BR * DIMG];
__device__ __align__(16) __nv_bfloat16 g_as_img_lo[BR * DIMG];
__device__ __align__(16) __nv_bfloat16 g_as_node_hi[N_NODES * DIN];
__device__ __align__(16) __nv_bfloat16 g_as_node_lo[N_NODES * DIN];
__device__ __align__(16) __nv_bfloat16 g_as_ap_hi[N_NODES * 1024];   // [msg | h1]
__device__ __align__(16) __nv_bfloat16 g_as_ap_lo[N_NODES * 1024];

// ---------------- helpers ----------------
__device__ __forceinline__ uint32_t smem_u32(const void* p) {
    uint32_t a;
    asm("{ .reg .u64 t; cvta.to.shared.u64 t, %1; cvt.u32.u64 %0, t; }" : "=r"(a) : "l"(p));
    return a;
}
__device__ __forceinline__ uint32_t pack_bf2(float f0, float f1) {
    uint32_t w;
    asm("cvt.rn.bf16x2.f32 %0, %1, %2;" : "=r"(w) : "f"(f1), "f"(f0));
    return w;
}
__device__ __forceinline__ void split2(float f0, float f1, uint32_t& whi, uint32_t& wlo) {
    whi = pack_bf2(f0, f1);
    float h0 = __uint_as_float(whi << 16);
    float h1 = __uint_as_float(whi & 0xffff0000u);
    wlo = pack_bf2(f0 - h0, f1 - h1);
}
__device__ __forceinline__ void mma_bf16(float* c, const uint32_t* a, uint32_t b0, uint32_t b1) {
    asm volatile(
        "mma.sync.aligned.m16n8k16.row.col.f32.bf16.bf16.f32 "
        "{%0,%1,%2,%3}, {%4,%5,%6,%7}, {%8,%9}, {%0,%1,%2,%3};\n"
        : "+f"(c[0]), "+f"(c[1]), "+f"(c[2]), "+f"(c[3])
        : "r"(a[0]), "r"(a[1]), "r"(a[2]), "r"(a[3]), "r"(b0), "r"(b1));
}
__device__ __forceinline__ void ldsm_x4(uint32_t& r0, uint32_t& r1, uint32_t& r2, uint32_t& r3,
                                        uint32_t addr) {
    asm volatile("ldmatrix.sync.aligned.m8n8.x4.shared.b16 {%0,%1,%2,%3}, [%4];"
                 : "=r"(r0), "=r"(r1), "=r"(r2), "=r"(r3) : "r"(addr));
}
#define CP_ASYNC16(dst, src) \
    asm volatile("cp.async.cg.shared.global [%0], [%1], 16;" :: "r"(dst), "l"(src))
#define CP_COMMIT() asm volatile("cp.async.commit_group;" ::: "memory")
#define CP_WAIT1()  asm volatile("cp.async.wait_group 1;" ::: "memory")
#define CP_WAIT0()  asm volatile("cp.async.wait_group 0;" ::: "memory")

// ---------------- Fused weight transpose + bf16 split (one launch, z picks weight) ----------------
__global__ void wt_all(const float* __restrict__ Wi, const float* __restrict__ Wim,
                       const float* __restrict__ Wf, const float* __restrict__ Wn,
                       const float* __restrict__ Wap,
                       __nv_bfloat16* __restrict__ ih, __nv_bfloat16* __restrict__ il,
                       __nv_bfloat16* __restrict__ nh, __nv_bfloat16* __restrict__ nl,
                       __nv_bfloat16* __restrict__ ah, __nv_bfloat16* __restrict__ al)
{
    const float* W; int K, N, rowoff, Kd;
    __nv_bfloat16 *hi, *lo;
    switch (blockIdx.z) {
        case 0:  W = Wi;  K = 1024; N = 256; hi = ih; lo = il; rowoff = 0;   Kd = 1024; break;
        case 1:  W = Wim; K = 1024; N = 512; hi = ih; lo = il; rowoff = 256; Kd = 1024; break;
        case 2:  W = Wf;  K = 512;  N = 256; hi = nh; lo = nl; rowoff = 0;   Kd = 512;  break;
        case 3:  W = Wn;  K = 512;  N = 512; hi = nh; lo = nl; rowoff = 256; Kd = 512;  break;
        default: W = Wap; K = 1024; N = 512; hi = ah; lo = al; rowoff = 0;   Kd = 1024; break;
    }
    const int n0 = blockIdx.x * 32, k0 = blockIdx.y * 32;
    if (n0 >= N || k0 >= K) return;

    __shared__ float tile[32][33];
    const int tx = threadIdx.x, ty = threadIdx.y;   // 32 x 8
    #pragma unroll
    for (int i = 0; i < 4; i++)
        tile[ty + i * 8][tx] = W[(size_t)(k0 + ty + i * 8) * N + n0 + tx];
    __syncthreads();
    #pragma unroll
    for (int i = 0; i < 4; i++) {
        int n = n0 + ty + i * 8, k = k0 + tx;
        float v = tile[tx][ty + i * 8];
        __nv_bfloat16 hh = __float2bfloat16(v);
        hi[(size_t)(rowoff + n) * Kd + k] = hh;
        lo[(size_t)(rowoff + n) * Kd + k] = __float2bfloat16(v - __bfloat162float(hh));
    }
}

// ---------------- Activation split: fp32 -> bf16 hi/lo ----------------
__global__ void split_kernel(const float4* __restrict__ in, int total4, int shift,
                             int pitch, int coloff,
                             __nv_bfloat16* __restrict__ hi, __nv_bfloat16* __restrict__ lo)
{
    int i = blockIdx.x * blockDim.x + threadIdx.x;
    if (i >= total4) return;
    int row = i >> shift;
    int c4 = i & ((1 << shift) - 1);
    float4 v = in[i];
    uint32_t h0, l0, h1, l1;
    split2(v.x, v.y, h0, l0);
    split2(v.z, v.w, h1, l1);
    size_t o = (size_t)row * pitch + coloff + c4 * 4;
    *(uint2*)(hi + o) = make_uint2(h0, h1);
    *(uint2*)(lo + o) = make_uint2(l0, l1);
}

// ================= bf16 3-term mma.sync GEMM v3 =================
// 512 threads / 16 warps, CTA tile 256(M)x128(N), warp tile 64x32 (4m x 4n warps),
// K-chunk 32, 3-stage cp.async pipeline, XOR-swizzled 64B-row smem.
// A and B pre-split bf16 [*, K] row-major. Two param sets via blockIdx.y (fused GEMMs).

struct GArg {
    const __nv_bfloat16* Ahi; const __nv_bfloat16* Alo; int Ap;
    const __nv_bfloat16* Bhi; const __nv_bfloat16* Blo; int K;
    const float* bias1; float* C1; int N1;
    const float* bias2; float* C2; int N2;
    int relu;
};

#define OFF_AL 16384
#define OFF_BH 32768
#define OFF_BL 40960
#define STAGE  49152
#define NS 3
#define GEMM_SMEM (NS * STAGE)
#define SWZ(r, c) ((((c) ^ (((r) >> 1) & 3))) << 4)

__global__ __launch_bounds__(512, 1) void gemm3(GArg ga, GArg gb, int ysplit) {
    extern __shared__ char sm[];
    const uint32_t sb = smem_u32(sm);
    const int tid = threadIdx.x;
    const int lane = tid & 31, warp = tid >> 5;
    const int wm = warp & 3, wn = warp >> 2;   // 4 x 4 warps: 64-row x 32-col tiles
    const int gid = lane >> 2, tig = lane & 3;

    const bool first = ((int)blockIdx.y < ysplit);
    const GArg g = first ? ga : gb;
    const int bm0 = (first ? (int)blockIdx.y : (int)blockIdx.y - ysplit) * 256;
    const int bn0 = (int)blockIdx.x * 128;

    const float* bias; float* C; int Nc, c0;
    if (bn0 < g.N1) { C = g.C1; bias = g.bias1; Nc = g.N1; c0 = bn0; }
    else            { C = g.C2; bias = g.bias2; Nc = g.N2; c0 = bn0 - g.N1; }

    const int T = g.K >> 5;

    // load mapping: A 256 rows x 4 16B-cols = 1024 slots (2/thread), B 128x4 = 512 (1/thread)
    const int ar1 = tid >> 1;                  // slot tid       -> row tid>>2? use two explicit slots
    // slot1 = tid, slot2 = tid + 512
    const int a1r = tid >> 2,        a1c = tid & 3;
    const int a2r = (tid + 512) >> 2, a2c = tid & 3;   // (tid+512)&3 == tid&3
    const int br  = tid >> 2,        bc  = tid & 3;
    (void)ar1;

    const char* gA1h = (const char*)(g.Ahi + (size_t)(bm0 + a1r) * g.Ap) + a1c * 16;
    const char* gA1l = (const char*)(g.Alo + (size_t)(bm0 + a1r) * g.Ap) + a1c * 16;
    const char* gA2h = (const char*)(g.Ahi + (size_t)(bm0 + a2r) * g.Ap) + a2c * 16;
    const char* gA2l = (const char*)(g.Alo + (size_t)(bm0 + a2r) * g.Ap) + a2c * 16;
    const char* gBh  = (const char*)(g.Bhi + (size_t)(bn0 + br) * g.K) + bc * 16;
    const char* gBl  = (const char*)(g.Blo + (size_t)(bn0 + br) * g.K) + bc * 16;
    const uint32_t d1 = (uint32_t)(a1r * 64 + SWZ(a1r, a1c));
    const uint32_t d2 = (uint32_t)(a2r * 64 + SWZ(a2r, a2c));
    const uint32_t db = (uint32_t)(br * 64 + SWZ(br, bc));

    #define ISSUE(t_, buf_) do {                                       \
        uint32_t base_ = sb + (buf_) * STAGE;                          \
        size_t go_ = (size_t)(t_) * 64;                                \
        CP_ASYNC16(base_ + d1,          gA1h + go_);                   \
        CP_ASYNC16(base_ + d1 + OFF_AL, gA1l + go_);                   \
        CP_ASYNC16(base_ + d2,          gA2h + go_);                   \
        CP_ASYNC16(base_ + d2 + OFF_AL, gA2l + go_);                   \
        CP_ASYNC16(base_ + db + OFF_BH, gBh + go_);                    \
        CP_ASYNC16(base_ + db + OFF_BL, gBl + go_);                    \
    } while (0)

    float c4[4][4][4];
    #pragma unroll
    for (int i = 0; i < 4; i++)
        #pragma unroll
        for (int j = 0; j < 4; j++)
            #pragma unroll
            for (int q = 0; q < 4; q++) c4[i][j][q] = 0.0f;

    // prologue
    ISSUE(0, 0); CP_COMMIT();
    if (T > 1) { ISSUE(1, 1); CP_COMMIT(); }

    for (int t = 0; t < T; t++) {
        if (t < T - 1) CP_WAIT1(); else CP_WAIT0();
        __syncthreads();
        if (t + 2 < T) { ISSUE(t + 2, (t + 2) % NS); CP_COMMIT(); }

        const uint32_t ss = sb + (uint32_t)(t % NS) * STAGE;
        #pragma unroll
        for (int kt = 0; kt < 2; kt++) {
            uint32_t ah[4][4], al[4][4];
            #pragma unroll
            for (int i = 0; i < 4; i++) {
                int ra = wm * 64 + i * 16 + (lane & 15);
                int ca = kt * 2 + (lane >> 4);
                uint32_t aa = ss + (uint32_t)(ra * 64 + SWZ(ra, ca));
                ldsm_x4(ah[i][0], ah[i][1], ah[i][2], ah[i][3], aa);
                ldsm_x4(al[i][0], al[i][1], al[i][2], al[i][3], aa + OFF_AL);
            }
            #pragma unroll
            for (int j2 = 0; j2 < 2; j2++) {
                int rb = wn * 32 + j2 * 16 + (lane & 7) + ((lane >> 4) << 3);
                int cb = kt * 2 + ((lane >> 3) & 1);
                uint32_t ba = ss + OFF_BH + (uint32_t)(rb * 64 + SWZ(rb, cb));
                uint32_t bh[4], bl[4];
                ldsm_x4(bh[0], bh[1], bh[2], bh[3], ba);
                ldsm_x4(bl[0], bl[1], bl[2], bl[3], ba + (OFF_BL - OFF_BH));
                #pragma unroll
                for (int jj = 0; jj < 2; jj++) {
                    #pragma unroll
                    for (int i = 0; i < 4; i++) {
                        float* cc = c4[i][j2 * 2 + jj];
                        mma_bf16(cc, ah[i], bh[jj * 2], bh[jj * 2 + 1]);
                        mma_bf16(cc, ah[i], bl[jj * 2], bl[jj * 2 + 1]);
                        mma_bf16(cc, al[i], bh[jj * 2], bh[jj * 2 + 1]);
                    }
                }
            }
        }
    }
    #undef ISSUE

    // ---- epilogue ----
    #pragma unroll
    for (int i = 0; i < 4; i++) {
        const int r0 = bm0 + wm * 64 + i * 16 + gid;
        #pragma unroll
        for (int j = 0; j < 4; j++) {
            const int col = c0 + wn * 32 + j * 8 + tig * 2;
            float bv0 = bias ? bias[col]     : 0.0f;
            float bv1 = bias ? bias[col + 1] : 0.0f;
            float v0 = c4[i][j][0] + bv0;
            float v1 = c4[i][j][1] + bv1;
            float v2 = c4[i][j][2] + bv0;
            float v3 = c4[i][j][3] + bv1;
            if (g.relu) {
                v0 = fmaxf(v0, 0.0f); v1 = fmaxf(v1, 0.0f);
                v2 = fmaxf(v2, 0.0f); v3 = fmaxf(v3, 0.0f);
            }
            C[(size_t)r0 * Nc + col]           = v0;
            C[(size_t)r0 * Nc + col + 1]       = v1;
            C[(size_t)(r0 + 8) * Nc + col]     = v2;
            C[(size_t)(r0 + 8) * Nc + col + 1] = v3;
        }
    }
}

// ---------------- Batch-grouped attention ----------------
#define ATT_SPLIT 2
#define ATT_SMEM_FLOATS (R_REG * PDIM + R_REG * DOUT + 8 * 40)
#define ATT_SMEM_BYTES  (ATT_SMEM_FLOATS * 4)

__device__ __forceinline__ float htanh(float x) {
    float y;
    asm("tanh.approx.f32 %0, %1;" : "=f"(y) : "f"(x));
    return y;
}

__global__ __launch_bounds__(256) void att2_kernel(
    const float* __restrict__ Wa, const float* __restrict__ ba,
    const float* __restrict__ bim)
{
    extern __shared__ float s_dyn[];
    float* s_ip  = s_dyn;
    float* s_fc  = s_dyn + R_REG * PDIM;
    float* s_att = s_dyn + R_REG * PDIM + R_REG * DOUT;

    const int b = blockIdx.y;
    const int s = blockIdx.x;
    const int tid = threadIdx.x;
    const int lane = tid & 31, warp = tid >> 5;

    {
        const float4* src1 = (const float4*)(g_img_proj + (size_t)b * R_REG * PDIM);
        float4* dst1 = (float4*)s_ip;
        for (int i = tid; i < R_REG * PDIM / 4; i += 256) dst1[i] = src1[i];
        const float4* src2 = (const float4*)(g_img_fc + (size_t)b * R_REG * DOUT);
        float4* dst2 = (float4*)s_fc;
        for (int i = tid; i < R_REG * DOUT / 4; i += 256) dst2[i] = src2[i];
    }
    __syncthreads();

    float wa[8];
    #pragma unroll
    for (int i = 0; i < 8; i++) wa[i] = Wa[lane + 32 * i];
    const float ba0 = ba[0];

    const int start = g_boff[b], end = g_boff[b + 1];
    float* sa = s_att + warp * 40;

    for (int idx = start + s * 8 + warp; idx < end; idx += ATT_SPLIT * 8) {
        const int n = g_bnodes[idx];

        float np[8];
        #pragma unroll
        for (int i = 0; i < 8; i++) np[i] = g_node_proj[(size_t)n * PDIM + lane + 32 * i];

        for (int r = 0; r < R_REG; r++) {
            const float* ip = s_ip + r * PDIM;
            float part = 0.0f;
            #pragma unroll
            for (int i = 0; i < 8; i++)
                part += htanh(np[i] + ip[lane + 32 * i]) * wa[i];
            #pragma unroll
            for (int o = 16; o > 0; o >>= 1) part += __shfl_xor_sync(0xffffffffu, part, o);
            if (lane == 0) sa[r] = part + ba0;
        }
        __syncwarp();

        {
            float v0 = sa[lane];
            float v1 = (lane < 4) ? sa[32 + lane] : -INFINITY;
            float m = fmaxf(v0, v1);
            #pragma unroll
            for (int o = 16; o > 0; o >>= 1) m = fmaxf(m, __shfl_xor_sync(0xffffffffu, m, o));
            float e0 = __expf(v0 - m);
            float e1 = (lane < 4) ? __expf(v1 - m) : 0.0f;
            float ssum = e0 + e1;
            #pragma unroll
            for (int o = 16; o > 0; o >>= 1) ssum += __shfl_xor_sync(0xffffffffu, ssum, o);
            float inv = 1.0f / ssum;
            sa[lane] = e0 * inv;
            if (lane < 4) sa[32 + lane] = e1 * inv;
        }
        __syncwarp();

        float4 acc[4];
        #pragma unroll
        for (int q = 0; q < 4; q++) acc[q] = make_float4(0.f, 0.f, 0.f, 0.f);
        for (int r = 0; r < R_REG; r++) {
            float a = sa[r];
            #pragma unroll
            for (int q = 0; q < 4; q++) {
                float4 v = *(const float4*)&s_fc[r * DOUT + q * 128 + lane * 4];
                acc[q].x += a * v.x; acc[q].y += a * v.y;
                acc[q].z += a * v.z; acc[q].w += a * v.w;
            }
        }
        #pragma unroll
        for (int q = 0; q < 4; q++) {
            float4 bvv = *(const float4*)&bim[q * 128 + lane * 4];
            acc[q].x += bvv.x; acc[q].y += bvv.y; acc[q].z += bvv.z; acc[q].w += bvv.w;
            *(float4*)&g_msg[(size_t)n * DOUT + q * 128 + lane * 4] = acc[q];
        }
        __syncwarp();
    }
}

// ---------------- CSR build ----------------
__global__ void zero_kernel() {
    int i = blockIdx.x * blockDim.x + threadIdx.x;
    if (i < N_NODES) { g_deg[i] = 0; g_cursor[i] = 0; }
    if (i < B_BATCH) { g_bdeg[i] = 0; g_bcur[i] = 0; }
}

__global__ void count_kernel(const int* __restrict__ dst, const int* __restrict__ batch_ids) {
    int e = blockIdx.x * blockDim.x + threadIdx.x;
    if (e < E_EDGES) atomicAdd(&g_deg[dst[e]], 1);
    if (e < N_NODES) atomicAdd(&g_bdeg[batch_ids[e]], 1);
}

__global__ void scan_kernel() {
    __shared__ int s[1024];
    const int tid = threadIdx.x;
    if (tid == 0) {
        int run = 0;
        for (int b = 0; b < B_BATCH; b++) { g_boff[b] = run; run += g_bdeg[b]; }
        g_boff[B_BATCH] = run;
    }
    const int chunk = N_NODES / 1024;
    const int base = tid * chunk;
    int sum = 0;
    #pragma unroll
    for (int i = 0; i < chunk; i++) sum += g_deg[base + i];
    s[tid] = sum;
    __syncthreads();
    for (int ofs = 1; ofs < 1024; ofs <<= 1) {
        int v = (tid >= ofs) ? s[tid - ofs] : 0;
        __syncthreads();
        if (tid >= ofs) s[tid] += v;
        __syncthreads();
    }
    int run = (tid == 0) ? 0 : s[tid - 1];
    #pragma unroll
    for (int i = 0; i < chunk; i++) {
        int idx = base + i;
        g_off[idx] = run;
        run += g_deg[idx];
    }
    if (tid == 0) g_off[N_NODES] = s[1023];
}

__global__ void fill_kernel(const int* __restrict__ src, const int* __restrict__ dst,
                            const int* __restrict__ batch_ids) {
    int e = blockIdx.x * blockDim.x + threadIdx.x;
    if (e < E_EDGES) {
        int d = dst[e];
        int pos = g_off[d] + atomicAdd(&g_cursor[d], 1);
        g_csr_src[pos] = src[e];
    }
    if (e < N_NODES) {
        int b = batch_ids[e];
        int pos = g_boff[b] + atomicAdd(&g_bcur[b], 1);
        g_bnodes[pos] = e;
    }
}

// ---------------- Neighbor sum + fused bf16 split of msg ----------------
__global__ __launch_bounds__(128) void neigh_kernel() {
    const int n = blockIdx.x;
    const int t = threadIdx.x;
    const int s0 = g_off[n], s1 = g_off[n + 1];
    float4 acc = make_float4(0.f, 0.f, 0.f, 0.f);
    const float4* h1v = (const float4*)g_h1;
    int e = s0;
    #pragma unroll 1
    for (; e + 4 <= s1; e += 4) {
        int a0 = g_csr_src[e + 0], a1 = g_csr_src[e + 1];
        int a2 = g_csr_src[e + 2], a3 = g_csr_src[e + 3];
        float4 v0 = h1v[(size_t)a0 * 128 + t];
        float4 v1 = h1v[(size_t)a1 * 128 + t];
        float4 v2 = h1v[(size_t)a2 * 128 + t];
        float4 v3 = h1v[(size_t)a3 * 128 + t];
        acc.x += v0.x + v1.x + v2.x + v3.x;
        acc.y += v0.y + v1.y + v2.y + v3.y;
        acc.z += v0.z + v1.z + v2.z + v3.z;
        acc.w += v0.w + v1.w + v2.w + v3.w;
    }
    for (; e < s1; e++) {
        int a = g_csr_src[e];
        float4 v = h1v[(size_t)a * 128 + t];
        acc.x += v.x; acc.y += v.y; acc.z += v.z; acc.w += v.w;
    }
    float4 m = ((const float4*)g_msg)[(size_t)n * 128 + t];
    m.x += acc.x; m.y += acc.y; m.z += acc.z; m.w += acc.w;
    uint32_t h0, l0, h1_, l1;
    split2(m.x, m.y, h0, l0);
    split2(m.z, m.w, h1_, l1);
    size_t o = (size_t)n * 1024 + t * 4;
    *(uint2*)(g_as_ap_hi + o) = make_uint2(h0, h1_);
    *(uint2*)(g_as_ap_lo + o) = make_uint2(l0, l1);
}

// ---------------- Host launcher ----------------
extern "C" void kernel_launch(void* const* d_in, const int* in_sizes, int n_in,
                              void* d_out, int out_size)
{
    const float* h         = (const float*)d_in[0];
    const float* img_feats = (const float*)d_in[1];
    const int*   batch_ids = (const int*)  d_in[2];
    const int*   src       = (const int*)  d_in[3];
    const int*   dst       = (const int*)  d_in[4];
    const float* Wf  = (const float*)d_in[5];
    const float* bf  = (const float*)d_in[6];
    const float* Wi  = (const float*)d_in[7];
    const float* bi  = (const float*)d_in[8];
    const float* Wa  = (const float*)d_in[9];
    const float* ba  = (const float*)d_in[10];
    const float* Wn  = (const float*)d_in[11];
    const float* bn  = (const float*)d_in[12];
    const float* Wim = (const float*)d_in[13];
    const float* bim = (const float*)d_in[14];
    const float* Wap = (const float*)d_in[15];
    const float* bap = (const float*)d_in[16];
    float* out = (float*)d_out;

    void *p_img_proj, *p_img_fc, *p_node_proj, *p_h1;
    void *p_wih, *p_wil, *p_wnh, *p_wnl, *p_wah, *p_wal;
    void *p_aih, *p_ail, *p_anh, *p_anl, *p_aph, *p_apl;
    cudaGetSymbolAddress(&p_img_proj,  g_img_proj);
    cudaGetSymbolAddress(&p_img_fc,    g_img_fc);
    cudaGetSymbolAddress(&p_node_proj, g_node_proj);
    cudaGetSymbolAddress(&p_h1,        g_h1);
    cudaGetSymbolAddress(&p_wih, g_wt_img_hi);
    cudaGetSymbolAddress(&p_wil, g_wt_img_lo);
    cudaGetSymbolAddress(&p_wnh, g_wt_node_hi);
    cudaGetSymbolAddress(&p_wnl, g_wt_node_lo);
    cudaGetSymbolAddress(&p_wah, g_wt_ap_hi);
    cudaGetSymbolAddress(&p_wal, g_wt_ap_lo);
    cudaGetSymbolAddress(&p_aih, g_as_img_hi);
    cudaGetSymbolAddress(&p_ail, g_as_img_lo);
    cudaGetSymbolAddress(&p_anh, g_as_node_hi);
    cudaGetSymbolAddress(&p_anl, g_as_node_lo);
    cudaGetSymbolAddress(&p_aph, g_as_ap_hi);
    cudaGetSymbolAddress(&p_apl, g_as_ap_lo);

    cudaFuncSetAttribute(att2_kernel,
                         cudaFuncAttributeMaxDynamicSharedMemorySize, ATT_SMEM_BYTES);
    cudaFuncSetAttribute(gemm3,
                         cudaFuncAttributeMaxDynamicSharedMemorySize, GEMM_SMEM);

    // 1-2: activation splits
    split_kernel<<<(BR * DIMG / 4 + 255) / 256, 256>>>(
        (const float4*)img_feats, BR * DIMG / 4, 8, 1024, 0,
        (__nv_bfloat16*)p_aih, (__nv_bfloat16*)p_ail);
    split_kernel<<<(N_NODES * DIN / 4 + 255) / 256, 256>>>(
        (const float4*)h, N_NODES * DIN / 4, 7, 512, 0,
        (__nv_bfloat16*)p_anh, (__nv_bfloat16*)p_anl);

    // 3: fused weight transpose+split (all 5 weights)
    wt_all<<<dim3(16, 32, 5), dim3(32, 8)>>>(
        Wi, Wim, Wf, Wn, Wap,
        (__nv_bfloat16*)p_wih, (__nv_bfloat16*)p_wil,
        (__nv_bfloat16*)p_wnh, (__nv_bfloat16*)p_wnl,
        (__nv_bfloat16*)p_wah, (__nv_bfloat16*)p_wal);

    // 4: fused GEMM (node [12288x768] y 0..47 + img [2304x768] y 48..56)
    GArg gnode, gimg, gap;
    gnode.Ahi = (const __nv_bfloat16*)p_anh; gnode.Alo = (const __nv_bfloat16*)p_anl;
    gnode.Ap = DIN;
    gnode.Bhi = (const __nv_bfloat16*)p_wnh; gnode.Blo = (const __nv_bfloat16*)p_wnl;
    gnode.K = DIN;
    gnode.bias1 = bf; gnode.C1 = (float*)p_node_proj; gnode.N1 = PDIM;
    gnode.bias2 = bn; gnode.C2 = (float*)p_h1;        gnode.N2 = DOUT;
    gnode.relu = 0;

    gimg.Ahi = (const __nv_bfloat16*)p_aih; gimg.Alo = (const __nv_bfloat16*)p_ail;
    gimg.Ap = DIMG;
    gimg.Bhi = (const __nv_bfloat16*)p_wih; gimg.Blo = (const __nv_bfloat16*)p_wil;
    gimg.K = DIMG;
    gimg.bias1 = bi;      gimg.C1 = (float*)p_img_proj; gimg.N1 = PDIM;
    gimg.bias2 = nullptr; gimg.C2 = (float*)p_img_fc;   gimg.N2 = DOUT;
    gimg.relu = 0;

    gemm3<<<dim3(6, 57), 512, GEMM_SMEM>>>(gnode, gimg, 48);

    // 5-8: CSR build
    zero_kernel<<<(N_NODES + 255) / 256, 256>>>();
    count_kernel<<<(E_EDGES + 255) / 256, 256>>>(dst, batch_ids);
    scan_kernel<<<1, 1024>>>();
    fill_kernel<<<(E_EDGES + 255) / 256, 256>>>(src, dst, batch_ids);

    // 9: h1 split into ap buffer columns 512..1023
    split_kernel<<<(N_NODES * DOUT / 4 + 255) / 256, 256>>>(
        (const float4*)p_h1, N_NODES * DOUT / 4, 7, 1024, 512,
        (__nv_bfloat16*)p_aph, (__nv_bfloat16*)p_apl);

    // 10: g_msg = bim + att @ img_fc
    att2_kernel<<<dim3(ATT_SPLIT, B_BATCH), 256, ATT_SMEM_BYTES>>>(Wa, ba, bim);

    // 11: msg += segment_sum(h1[src], dst); split into ap columns 0..511
    neigh_kernel<<<N_NODES, 128>>>();

    // 12: out = relu([msg | h1] @ Wap + bap)
    gap.Ahi = (const __nv_bfloat16*)p_aph; gap.Alo = (const __nv_bfloat16*)p_apl;
    gap.Ap = 1024;
    gap.Bhi = (const __nv_bfloat16*)p_wah; gap.Blo = (const __nv_bfloat16*)p_wal;
    gap.K = 1024;
    gap.bias1 = bap; gap.C1 = out; gap.N1 = DOUT;
    gap.bias2 = nullptr; gap.C2 = nullptr; gap.N2 = 0;
    gap.relu = 1;

    gemm3<<<dim3(4, 48), 512, GEMM_SMEM>>>(gap, gap, 48);
}

// round 13
// speedup vs baseline: 1.0038x; 1.0038x over previous
#include <cuda_runtime.h>
#include <cuda_bf16.h>
#include <math.h>
#include <stdint.h>

// ---------------- Problem constants ----------------
#define N_NODES 12288
#define B_BATCH 64
#define R_REG   36
#define E_EDGES 196608
#define DIN     512
#define DOUT    512
#define PDIM    256
#define DIMG    1024
#define BR      (B_BATCH * R_REG)   // 2304

// ---------------- Scratch (device globals; no allocation allowed) ----------------
__device__ __align__(16) float g_img_proj[BR * PDIM];
__device__ __align__(16) float g_img_fc[BR * DOUT];
__device__ __align__(16) float g_node_proj[N_NODES * PDIM];
__device__ __align__(16) float g_h1[N_NODES * DOUT];
__device__ __align__(16) float g_msg[N_NODES * DOUT];
__device__ int g_deg[N_NODES];
__device__ int g_cursor[N_NODES];
__device__ int g_off[N_NODES + 1];
__device__ int g_csr_src[E_EDGES];
__device__ int g_bdeg[B_BATCH];
__device__ int g_bcur[B_BATCH];
__device__ int g_boff[B_BATCH + 1];
__device__ int g_bnodes[N_NODES];
// Pre-transposed, bf16 hi/lo split weights, [N,K] row-major
__device__ __align__(16) __nv_bfloat16 g_wt_img_hi[768 * 1024];
__device__ __align__(16) __nv_bfloat16 g_wt_img_lo[768 * 1024];
__device__ __align__(16) __nv_bfloat16 g_wt_node_hi[768 * 512];
__device__ __align__(16) __nv_bfloat16 g_wt_node_lo[768 * 512];
__device__ __align__(16) __nv_bfloat16 g_wt_ap_hi[512 * 1024];
__device__ __align__(16) __nv_bfloat16 g_wt_ap_lo[512 * 1024];
// Pre-split activations, bf16 hi/lo, row-major
__device__ __align__(16) __nv_bfloat16 g_as_img_hi[BR * DIMG];
__device__ __align__(16) __nv_bfloat16 g_as_img_lo[BR * DIMG];
__device__ __align__(16) __nv_bfloat16 g_as_node_hi[N_NODES * DIN];
__device__ __align__(16) __nv_bfloat16 g_as_node_lo[N_NODES * DIN];
__device__ __align__(16) __nv_bfloat16 g_as_ap_hi[N_NODES * 1024];   // [msg | h1]
__device__ __align__(16) __nv_bfloat16 g_as_ap_lo[N_NODES * 1024];

// ---------------- helpers ----------------
__device__ __forceinline__ uint32_t smem_u32(const void* p) {
    uint32_t a;
    asm("{ .reg .u64 t; cvta.to.shared.u64 t, %1; cvt.u32.u64 %0, t; }" : "=r"(a) : "l"(p));
    return a;
}
__device__ __forceinline__ uint32_t pack_bf2(float f0, float f1) {
    uint32_t w;
    asm("cvt.rn.bf16x2.f32 %0, %1, %2;" : "=r"(w) : "f"(f1), "f"(f0));
    return w;
}
__device__ __forceinline__ void split2(float f0, float f1, uint32_t& whi, uint32_t& wlo) {
    whi = pack_bf2(f0, f1);
    float h0 = __uint_as_float(whi << 16);
    float h1 = __uint_as_float(whi & 0xffff0000u);
    wlo = pack_bf2(f0 - h0, f1 - h1);
}
__device__ __forceinline__ void mma_bf16(float* c, const uint32_t* a, uint32_t b0, uint32_t b1) {
    asm volatile(
        "mma.sync.aligned.m16n8k16.row.col.f32.bf16.bf16.f32 "
        "{%0,%1,%2,%3}, {%4,%5,%6,%7}, {%8,%9}, {%0,%1,%2,%3};\n"
        : "+f"(c[0]), "+f"(c[1]), "+f"(c[2]), "+f"(c[3])
        : "r"(a[0]), "r"(a[1]), "r"(a[2]), "r"(a[3]), "r"(b0), "r"(b1));
}
__device__ __forceinline__ void ldsm_x4(uint32_t& r0, uint32_t& r1, uint32_t& r2, uint32_t& r3,
                                        uint32_t addr) {
    asm volatile("ldmatrix.sync.aligned.m8n8.x4.shared.b16 {%0,%1,%2,%3}, [%4];"
                 : "=r"(r0), "=r"(r1), "=r"(r2), "=r"(r3) : "r"(addr));
}
#define CP_ASYNC16(dst, src) \
    asm volatile("cp.async.cg.shared.global [%0], [%1], 16;" :: "r"(dst), "l"(src))
#define CP_COMMIT() asm volatile("cp.async.commit_group;" ::: "memory")
#define CP_WAIT1()  asm volatile("cp.async.wait_group 1;" ::: "memory")
#define CP_WAIT0()  asm volatile("cp.async.wait_group 0;" ::: "memory")

// ---------------- Fused weight transpose + bf16 split (one launch, z picks weight) ----------------
__global__ void wt_all(const float* __restrict__ Wi, const float* __restrict__ Wim,
                       const float* __restrict__ Wf, const float* __restrict__ Wn,
                       const float* __restrict__ Wap,
                       __nv_bfloat16* __restrict__ ih, __nv_bfloat16* __restrict__ il,
                       __nv_bfloat16* __restrict__ nh, __nv_bfloat16* __restrict__ nl,
                       __nv_bfloat16* __restrict__ ah, __nv_bfloat16* __restrict__ al)
{
    const float* W; int K, N, rowoff, Kd;
    __nv_bfloat16 *hi, *lo;
    switch (blockIdx.z) {
        case 0:  W = Wi;  K = 1024; N = 256; hi = ih; lo = il; rowoff = 0;   Kd = 1024; break;
        case 1:  W = Wim; K = 1024; N = 512; hi = ih; lo = il; rowoff = 256; Kd = 1024; break;
        case 2:  W = Wf;  K = 512;  N = 256; hi = nh; lo = nl; rowoff = 0;   Kd = 512;  break;
        case 3:  W = Wn;  K = 512;  N = 512; hi = nh; lo = nl; rowoff = 256; Kd = 512;  break;
        default: W = Wap; K = 1024; N = 512; hi = ah; lo = al; rowoff = 0;   Kd = 1024; break;
    }
    const int n0 = blockIdx.x * 32, k0 = blockIdx.y * 32;
    if (n0 >= N || k0 >= K) return;

    __shared__ float tile[32][33];
    const int tx = threadIdx.x, ty = threadIdx.y;   // 32 x 8
    #pragma unroll
    for (int i = 0; i < 4; i++)
        tile[ty + i * 8][tx] = W[(size_t)(k0 + ty + i * 8) * N + n0 + tx];
    __syncthreads();
    #pragma unroll
    for (int i = 0; i < 4; i++) {
        int n = n0 + ty + i * 8, k = k0 + tx;
        float v = tile[tx][ty + i * 8];
        __nv_bfloat16 hh = __float2bfloat16(v);
        hi[(size_t)(rowoff + n) * Kd + k] = hh;
        lo[(size_t)(rowoff + n) * Kd + k] = __float2bfloat16(v - __bfloat162float(hh));
    }
}

// ---------------- Activation split: fp32 -> bf16 hi/lo ----------------
__global__ void split_kernel(const float4* __restrict__ in, int total4, int shift,
                             int pitch, int coloff,
                             __nv_bfloat16* __restrict__ hi, __nv_bfloat16* __restrict__ lo)
{
    int i = blockIdx.x * blockDim.x + threadIdx.x;
    if (i >= total4) return;
    int row = i >> shift;
    int c4 = i & ((1 << shift) - 1);
    float4 v = in[i];
    uint32_t h0, l0, h1, l1;
    split2(v.x, v.y, h0, l0);
    split2(v.z, v.w, h1, l1);
    size_t o = (size_t)row * pitch + coloff + c4 * 4;
    *(uint2*)(hi + o) = make_uint2(h0, h1);
    *(uint2*)(lo + o) = make_uint2(l0, l1);
}

// ================= bf16 3-term mma.sync GEMM v3 =================
// 512 threads / 16 warps, CTA tile 256(M)x128(N), warp tile 64x32 (4m x 4n warps),
// K-chunk 32, 3-stage cp.async pipeline, XOR-swizzled 64B-row smem.
// A and B pre-split bf16 [*, K] row-major. Two param sets via blockIdx.y (fused GEMMs).

struct GArg {
    const __nv_bfloat16* Ahi; const __nv_bfloat16* Alo; int Ap;
    const __nv_bfloat16* Bhi; const __nv_bfloat16* Blo; int K;
    const float* bias1; float* C1; int N1;
    const float* bias2; float* C2; int N2;
    int relu;
};

#define OFF_AL 16384
#define OFF_BH 32768
#define OFF_BL 40960
#define STAGE  49152
#define NS 3
#define GEMM_SMEM (NS * STAGE)
#define SWZ(r, c) ((((c) ^ (((r) >> 1) & 3))) << 4)

__global__ __launch_bounds__(512, 1) void gemm3(GArg ga, GArg gb, int ysplit) {
    extern __shared__ char sm[];
    const uint32_t sb = smem_u32(sm);
    const int tid = threadIdx.x;
    const int lane = tid & 31, warp = tid >> 5;
    const int wm = warp & 3, wn = warp >> 2;   // 4 x 4 warps: 64-row x 32-col tiles
    const int gid = lane >> 2, tig = lane & 3;

    const bool first = ((int)blockIdx.y < ysplit);
    const GArg g = first ? ga : gb;
    const int bm0 = (first ? (int)blockIdx.y : (int)blockIdx.y - ysplit) * 256;
    const int bn0 = (int)blockIdx.x * 128;

    const float* bias; float* C; int Nc, c0;
    if (bn0 < g.N1) { C = g.C1; bias = g.bias1; Nc = g.N1; c0 = bn0; }
    else            { C = g.C2; bias = g.bias2; Nc = g.N2; c0 = bn0 - g.N1; }

    const int T = g.K >> 5;

    // load mapping: A 256 rows x 4 16B-cols = 1024 slots (2/thread), B 128x4 = 512 (1/thread)
    const int a1r = tid >> 2,         a1c = tid & 3;
    const int a2r = (tid + 512) >> 2, a2c = tid & 3;
    const int br  = tid >> 2,         bc  = tid & 3;

    const char* gA1h = (const char*)(g.Ahi + (size_t)(bm0 + a1r) * g.Ap) + a1c * 16;
    const char* gA1l = (const char*)(g.Alo + (size_t)(bm0 + a1r) * g.Ap) + a1c * 16;
    const char* gA2h = (const char*)(g.Ahi + (size_t)(bm0 + a2r) * g.Ap) + a2c * 16;
    const char* gA2l = (const char*)(g.Alo + (size_t)(bm0 + a2r) * g.Ap) + a2c * 16;
    const char* gBh  = (const char*)(g.Bhi + (size_t)(bn0 + br) * g.K) + bc * 16;
    const char* gBl  = (const char*)(g.Blo + (size_t)(bn0 + br) * g.K) + bc * 16;
    const uint32_t d1 = (uint32_t)(a1r * 64 + SWZ(a1r, a1c));
    const uint32_t d2 = (uint32_t)(a2r * 64 + SWZ(a2r, a2c));
    const uint32_t db = (uint32_t)(br * 64 + SWZ(br, bc));

    #define ISSUE(t_, buf_) do {                                       \
        uint32_t base_ = sb + (buf_) * STAGE;                          \
        size_t go_ = (size_t)(t_) * 64;                                \
        CP_ASYNC16(base_ + d1,          gA1h + go_);                   \
        CP_ASYNC16(base_ + d1 + OFF_AL, gA1l + go_);                   \
        CP_ASYNC16(base_ + d2,          gA2h + go_);                   \
        CP_ASYNC16(base_ + d2 + OFF_AL, gA2l + go_);                   \
        CP_ASYNC16(base_ + db + OFF_BH, gBh + go_);                    \
        CP_ASYNC16(base_ + db + OFF_BL, gBl + go_);                    \
    } while (0)

    float c4[4][4][4];
    #pragma unroll
    for (int i = 0; i < 4; i++)
        #pragma unroll
        for (int j = 0; j < 4; j++)
            #pragma unroll
            for (int q = 0; q < 4; q++) c4[i][j][q] = 0.0f;

    // prologue
    ISSUE(0, 0); CP_COMMIT();
    if (T > 1) { ISSUE(1, 1); CP_COMMIT(); }

    for (int t = 0; t < T; t++) {
        if (t < T - 1) CP_WAIT1(); else CP_WAIT0();
        __syncthreads();
        if (t + 2 < T) { ISSUE(t + 2, (t + 2) % NS); CP_COMMIT(); }

        const uint32_t ss = sb + (uint32_t)(t % NS) * STAGE;
        #pragma unroll
        for (int kt = 0; kt < 2; kt++) {
            uint32_t ah[4][4], al[4][4];
            #pragma unroll
            for (int i = 0; i < 4; i++) {
                int ra = wm * 64 + i * 16 + (lane & 15);
                int ca = kt * 2 + (lane >> 4);
                uint32_t aa = ss + (uint32_t)(ra * 64 + SWZ(ra, ca));
                ldsm_x4(ah[i][0], ah[i][1], ah[i][2], ah[i][3], aa);
                ldsm_x4(al[i][0], al[i][1], al[i][2], al[i][3], aa + OFF_AL);
            }
            #pragma unroll
            for (int j2 = 0; j2 < 2; j2++) {
                int rb = wn * 32 + j2 * 16 + (lane & 7) + ((lane >> 4) << 3);
                int cb = kt * 2 + ((lane >> 3) & 1);
                uint32_t ba = ss + OFF_BH + (uint32_t)(rb * 64 + SWZ(rb, cb));
                uint32_t bh[4], bl[4];
                ldsm_x4(bh[0], bh[1], bh[2], bh[3], ba);
                ldsm_x4(bl[0], bl[1], bl[2], bl[3], ba + (OFF_BL - OFF_BH));
                #pragma unroll
                for (int jj = 0; jj < 2; jj++) {
                    #pragma unroll
                    for (int i = 0; i < 4; i++) {
                        float* cc = c4[i][j2 * 2 + jj];
                        mma_bf16(cc, ah[i], bh[jj * 2], bh[jj * 2 + 1]);
                        mma_bf16(cc, ah[i], bl[jj * 2], bl[jj * 2 + 1]);
                        mma_bf16(cc, al[i], bh[jj * 2], bh[jj * 2 + 1]);
                    }
                }
            }
        }
    }
    #undef ISSUE

    // ---- epilogue ----
    #pragma unroll
    for (int i = 0; i < 4; i++) {
        const int r0 = bm0 + wm * 64 + i * 16 + gid;
        #pragma unroll
        for (int j = 0; j < 4; j++) {
            const int col = c0 + wn * 32 + j * 8 + tig * 2;
            float bv0 = bias ? bias[col]     : 0.0f;
            float bv1 = bias ? bias[col + 1] : 0.0f;
            float v0 = c4[i][j][0] + bv0;
            float v1 = c4[i][j][1] + bv1;
            float v2 = c4[i][j][2] + bv0;
            float v3 = c4[i][j][3] + bv1;
            if (g.relu) {
                v0 = fmaxf(v0, 0.0f); v1 = fmaxf(v1, 0.0f);
                v2 = fmaxf(v2, 0.0f); v3 = fmaxf(v3, 0.0f);
            }
            C[(size_t)r0 * Nc + col]           = v0;
            C[(size_t)r0 * Nc + col + 1]       = v1;
            C[(size_t)(r0 + 8) * Nc + col]     = v2;
            C[(size_t)(r0 + 8) * Nc + col + 1] = v3;
        }
    }
}

// ---------------- Batch-grouped attention ----------------
#define ATT_SPLIT 2
#define ATT_SMEM_FLOATS (R_REG * PDIM + R_REG * DOUT + 8 * 40)
#define ATT_SMEM_BYTES  (ATT_SMEM_FLOATS * 4)

__device__ __forceinline__ float htanh(float x) {
    float y;
    asm("tanh.approx.f32 %0, %1;" : "=f"(y) : "f"(x));
    return y;
}

__global__ __launch_bounds__(256) void att2_kernel(
    const float* __restrict__ Wa, const float* __restrict__ ba,
    const float* __restrict__ bim)
{
    extern __shared__ float s_dyn[];
    float* s_ip  = s_dyn;
    float* s_fc  = s_dyn + R_REG * PDIM;
    float* s_att = s_dyn + R_REG * PDIM + R_REG * DOUT;

    const int b = blockIdx.y;
    const int s = blockIdx.x;
    const int tid = threadIdx.x;
    const int lane = tid & 31, warp = tid >> 5;

    {
        const float4* src1 = (const float4*)(g_img_proj + (size_t)b * R_REG * PDIM);
        float4* dst1 = (float4*)s_ip;
        for (int i = tid; i < R_REG * PDIM / 4; i += 256) dst1[i] = src1[i];
        const float4* src2 = (const float4*)(g_img_fc + (size_t)b * R_REG * DOUT);
        float4* dst2 = (float4*)s_fc;
        for (int i = tid; i < R_REG * DOUT / 4; i += 256) dst2[i] = src2[i];
    }
    __syncthreads();

    float wa[8];
    #pragma unroll
    for (int i = 0; i < 8; i++) wa[i] = Wa[lane + 32 * i];
    const float ba0 = ba[0];

    const int start = g_boff[b], end = g_boff[b + 1];
    float* sa = s_att + warp * 40;

    for (int idx = start + s * 8 + warp; idx < end; idx += ATT_SPLIT * 8) {
        const int n = g_bnodes[idx];

        float np[8];
        #pragma unroll
        for (int i = 0; i < 8; i++) np[i] = g_node_proj[(size_t)n * PDIM + lane + 32 * i];

        for (int r = 0; r < R_REG; r++) {
            const float* ip = s_ip + r * PDIM;
            float part = 0.0f;
            #pragma unroll
            for (int i = 0; i < 8; i++)
                part += htanh(np[i] + ip[lane + 32 * i]) * wa[i];
            #pragma unroll
            for (int o = 16; o > 0; o >>= 1) part += __shfl_xor_sync(0xffffffffu, part, o);
            if (lane == 0) sa[r] = part + ba0;
        }
        __syncwarp();

        {
            float v0 = sa[lane];
            float v1 = (lane < 4) ? sa[32 + lane] : -INFINITY;
            float m = fmaxf(v0, v1);
            #pragma unroll
            for (int o = 16; o > 0; o >>= 1) m = fmaxf(m, __shfl_xor_sync(0xffffffffu, m, o));
            float e0 = __expf(v0 - m);
            float e1 = (lane < 4) ? __expf(v1 - m) : 0.0f;
            float ssum = e0 + e1;
            #pragma unroll
            for (int o = 16; o > 0; o >>= 1) ssum += __shfl_xor_sync(0xffffffffu, ssum, o);
            float inv = 1.0f / ssum;
            sa[lane] = e0 * inv;
            if (lane < 4) sa[32 + lane] = e1 * inv;
        }
        __syncwarp();

        float4 acc[4];
        #pragma unroll
        for (int q = 0; q < 4; q++) acc[q] = make_float4(0.f, 0.f, 0.f, 0.f);
        for (int r = 0; r < R_REG; r++) {
            float a = sa[r];
            #pragma unroll
            for (int q = 0; q < 4; q++) {
                float4 v = *(const float4*)&s_fc[r * DOUT + q * 128 + lane * 4];
                acc[q].x += a * v.x; acc[q].y += a * v.y;
                acc[q].z += a * v.z; acc[q].w += a * v.w;
            }
        }
        #pragma unroll
        for (int q = 0; q < 4; q++) {
            float4 bvv = *(const float4*)&bim[q * 128 + lane * 4];
            acc[q].x += bvv.x; acc[q].y += bvv.y; acc[q].z += bvv.z; acc[q].w += bvv.w;
            *(float4*)&g_msg[(size_t)n * DOUT + q * 128 + lane * 4] = acc[q];
        }
        __syncwarp();
    }
}

// ---------------- CSR build ----------------
__global__ void zero_kernel() {
    int i = blockIdx.x * blockDim.x + threadIdx.x;
    if (i < N_NODES) { g_deg[i] = 0; g_cursor[i] = 0; }
    if (i < B_BATCH) { g_bdeg[i] = 0; g_bcur[i] = 0; }
}

__global__ void count_kernel(const int* __restrict__ dst, const int* __restrict__ batch_ids) {
    int e = blockIdx.x * blockDim.x + threadIdx.x;
    if (e < E_EDGES) atomicAdd(&g_deg[dst[e]], 1);
    if (e < N_NODES) atomicAdd(&g_bdeg[batch_ids[e]], 1);
}

__global__ void scan_kernel() {
    __shared__ int s[1024];
    const int tid = threadIdx.x;
    if (tid == 0) {
        int run = 0;
        for (int b = 0; b < B_BATCH; b++) { g_boff[b] = run; run += g_bdeg[b]; }
        g_boff[B_BATCH] = run;
    }
    const int chunk = N_NODES / 1024;
    const int base = tid * chunk;
    int sum = 0;
    #pragma unroll
    for (int i = 0; i < chunk; i++) sum += g_deg[base + i];
    s[tid] = sum;
    __syncthreads();
    for (int ofs = 1; ofs < 1024; ofs <<= 1) {
        int v = (tid >= ofs) ? s[tid - ofs] : 0;
        __syncthreads();
        if (tid >= ofs) s[tid] += v;
        __syncthreads();
    }
    int run = (tid == 0) ? 0 : s[tid - 1];
    #pragma unroll
    for (int i = 0; i < chunk; i++) {
        int idx = base + i;
        g_off[idx] = run;
        run += g_deg[idx];
    }
    if (tid == 0) g_off[N_NODES] = s[1023];
}

__global__ void fill_kernel(const int* __restrict__ src, const int* __restrict__ dst,
                            const int* __restrict__ batch_ids) {
    int e = blockIdx.x * blockDim.x + threadIdx.x;
    if (e < E_EDGES) {
        int d = dst[e];
        int pos = g_off[d] + atomicAdd(&g_cursor[d], 1);
        g_csr_src[pos] = src[e];
    }
    if (e < N_NODES) {
        int b = batch_ids[e];
        int pos = g_boff[b] + atomicAdd(&g_bcur[b], 1);
        g_bnodes[pos] = e;
    }
}

// ---------------- Neighbor sum + fused bf16 split of msg ----------------
__global__ __launch_bounds__(128) void neigh_kernel() {
    const int n = blockIdx.x;
    const int t = threadIdx.x;
    const int s0 = g_off[n], s1 = g_off[n + 1];
    float4 acc = make_float4(0.f, 0.f, 0.f, 0.f);
    const float4* h1v = (const float4*)g_h1;
    int e = s0;
    #pragma unroll 1
    for (; e + 4 <= s1; e += 4) {
        int a0 = g_csr_src[e + 0], a1 = g_csr_src[e + 1];
        int a2 = g_csr_src[e + 2], a3 = g_csr_src[e + 3];
        float4 v0 = h1v[(size_t)a0 * 128 + t];
        float4 v1 = h1v[(size_t)a1 * 128 + t];
        float4 v2 = h1v[(size_t)a2 * 128 + t];
        float4 v3 = h1v[(size_t)a3 * 128 + t];
        acc.x += v0.x + v1.x + v2.x + v3.x;
        acc.y += v0.y + v1.y + v2.y + v3.y;
        acc.z += v0.z + v1.z + v2.z + v3.z;
        acc.w += v0.w + v1.w + v2.w + v3.w;
    }
    for (; e < s1; e++) {
        int a = g_csr_src[e];
        float4 v = h1v[(size_t)a * 128 + t];
        acc.x += v.x; acc.y += v.y; acc.z += v.z; acc.w += v.w;
    }
    float4 m = ((const float4*)g_msg)[(size_t)n * 128 + t];
    m.x += acc.x; m.y += acc.y; m.z += acc.z; m.w += acc.w;
    uint32_t h0, l0, h1_, l1;
    split2(m.x, m.y, h0, l0);
    split2(m.z, m.w, h1_, l1);
    size_t o = (size_t)n * 1024 + t * 4;
    *(uint2*)(g_as_ap_hi + o) = make_uint2(h0, h1_);
    *(uint2*)(g_as_ap_lo + o) = make_uint2(l0, l1);
}

// ---------------- Host launcher ----------------
extern "C" void kernel_launch(void* const* d_in, const int* in_sizes, int n_in,
                              void* d_out, int out_size)
{
    const float* h         = (const float*)d_in[0];
    const float* img_feats = (const float*)d_in[1];
    const int*   batch_ids = (const int*)  d_in[2];
    const int*   src       = (const int*)  d_in[3];
    const int*   dst       = (const int*)  d_in[4];
    const float* Wf  = (const float*)d_in[5];
    const float* bf  = (const float*)d_in[6];
    const float* Wi  = (const float*)d_in[7];
    const float* bi  = (const float*)d_in[8];
    const float* Wa  = (const float*)d_in[9];
    const float* ba  = (const float*)d_in[10];
    const float* Wn  = (const float*)d_in[11];
    const float* bn  = (const float*)d_in[12];
    const float* Wim = (const float*)d_in[13];
    const float* bim = (const float*)d_in[14];
    const float* Wap = (const float*)d_in[15];
    const float* bap = (const float*)d_in[16];
    float* out = (float*)d_out;

    void *p_img_proj, *p_img_fc, *p_node_proj, *p_h1;
    void *p_wih, *p_wil, *p_wnh, *p_wnl, *p_wah, *p_wal;
    void *p_aih, *p_ail, *p_anh, *p_anl, *p_aph, *p_apl;
    cudaGetSymbolAddress(&p_img_proj,  g_img_proj);
    cudaGetSymbolAddress(&p_img_fc,    g_img_fc);
    cudaGetSymbolAddress(&p_node_proj, g_node_proj);
    cudaGetSymbolAddress(&p_h1,        g_h1);
    cudaGetSymbolAddress(&p_wih, g_wt_img_hi);
    cudaGetSymbolAddress(&p_wil, g_wt_img_lo);
    cudaGetSymbolAddress(&p_wnh, g_wt_node_hi);
    cudaGetSymbolAddress(&p_wnl, g_wt_node_lo);
    cudaGetSymbolAddress(&p_wah, g_wt_ap_hi);
    cudaGetSymbolAddress(&p_wal, g_wt_ap_lo);
    cudaGetSymbolAddress(&p_aih, g_as_img_hi);
    cudaGetSymbolAddress(&p_ail, g_as_img_lo);
    cudaGetSymbolAddress(&p_anh, g_as_node_hi);
    cudaGetSymbolAddress(&p_anl, g_as_node_lo);
    cudaGetSymbolAddress(&p_aph, g_as_ap_hi);
    cudaGetSymbolAddress(&p_apl, g_as_ap_lo);

    cudaFuncSetAttribute(att2_kernel,
                         cudaFuncAttributeMaxDynamicSharedMemorySize, ATT_SMEM_BYTES);
    cudaFuncSetAttribute(gemm3,
                         cudaFuncAttributeMaxDynamicSharedMemorySize, GEMM_SMEM);

    // 1-2: activation splits
    split_kernel<<<(BR * DIMG / 4 + 255) / 256, 256>>>(
        (const float4*)img_feats, BR * DIMG / 4, 8, 1024, 0,
        (__nv_bfloat16*)p_aih, (__nv_bfloat16*)p_ail);
    split_kernel<<<(N_NODES * DIN / 4 + 255) / 256, 256>>>(
        (const float4*)h, N_NODES * DIN / 4, 7, 512, 0,
        (__nv_bfloat16*)p_anh, (__nv_bfloat16*)p_anl);

    // 3: fused weight transpose+split (all 5 weights)
    wt_all<<<dim3(16, 32, 5), dim3(32, 8)>>>(
        Wi, Wim, Wf, Wn, Wap,
        (__nv_bfloat16*)p_wih, (__nv_bfloat16*)p_wil,
        (__nv_bfloat16*)p_wnh, (__nv_bfloat16*)p_wnl,
        (__nv_bfloat16*)p_wah, (__nv_bfloat16*)p_wal);

    // 4: fused GEMM (node [12288x768] y 0..47 + img [2304x768] y 48..56)
    GArg gnode, gimg, gap;
    gnode.Ahi = (const __nv_bfloat16*)p_anh; gnode.Alo = (const __nv_bfloat16*)p_anl;
    gnode.Ap = DIN;
    gnode.Bhi = (const __nv_bfloat16*)p_wnh; gnode.Blo = (const __nv_bfloat16*)p_wnl;
    gnode.K = DIN;
    gnode.bias1 = bf; gnode.C1 = (float*)p_node_proj; gnode.N1 = PDIM;
    gnode.bias2 = bn; gnode.C2 = (float*)p_h1;        gnode.N2 = DOUT;
    gnode.relu = 0;

    gimg.Ahi = (const __nv_bfloat16*)p_aih; gimg.Alo = (const __nv_bfloat16*)p_ail;
    gimg.Ap = DIMG;
    gimg.Bhi = (const __nv_bfloat16*)p_wih; gimg.Blo = (const __nv_bfloat16*)p_wil;
    gimg.K = DIMG;
    gimg.bias1 = bi;      gimg.C1 = (float*)p_img_proj; gimg.N1 = PDIM;
    gimg.bias2 = nullptr; gimg.C2 = (float*)p_img_fc;   gimg.N2 = DOUT;
    gimg.relu = 0;

    gemm3<<<dim3(6, 57), 512, GEMM_SMEM>>>(gnode, gimg, 48);

    // 5-8: CSR build
    zero_kernel<<<(N_NODES + 255) / 256, 256>>>();
    count_kernel<<<(E_EDGES + 255) / 256, 256>>>(dst, batch_ids);
    scan_kernel<<<1, 1024>>>();
    fill_kernel<<<(E_EDGES + 255) / 256, 256>>>(src, dst, batch_ids);

    // 9: h1 split into ap buffer columns 512..1023
    split_kernel<<<(N_NODES * DOUT / 4 + 255) / 256, 256>>>(
        (const float4*)p_h1, N_NODES * DOUT / 4, 7, 1024, 512,
        (__nv_bfloat16*)p_aph, (__nv_bfloat16*)p_apl);

    // 10: g_msg = bim + att @ img_fc
    att2_kernel<<<dim3(ATT_SPLIT, B_BATCH), 256, ATT_SMEM_BYTES>>>(Wa, ba, bim);

    // 11: msg += segment_sum(h1[src], dst); split into ap columns 0..511
    neigh_kernel<<<N_NODES, 128>>>();

    // 12: out = relu([msg | h1] @ Wap + bap)
    gap.Ahi = (const __nv_bfloat16*)p_aph; gap.Alo = (const __nv_bfloat16*)p_apl;
    gap.Ap = 1024;
    gap.Bhi = (const __nv_bfloat16*)p_wah; gap.Blo = (const __nv_bfloat16*)p_wal;
    gap.K = 1024;
    gap.bias1 = bap; gap.C1 = out; gap.N1 = DOUT;
    gap.bias2 = nullptr; gap.C2 = nullptr; gap.N2 = 0;
    gap.relu = 1;

    gemm3<<<dim3(4, 48), 512, GEMM_SMEM>>>(gap, gap, 48);
}